// round 3
// baseline (speedup 1.0000x reference)
#include <cuda_runtime.h>
#include <math.h>

#define TT    64
#define BB    2048
#define LAT   128
#define OBSD  128
#define CTRL  16
#define NMATD 16
#define HH    128

// ---------------- scratch (no allocation allowed) ----------------
__device__ float g_h0[BB * HH];
__device__ float g_h1[BB * HH];
__device__ float g_c[BB * HH];
__device__ float g_hbuf[BB * HH];
__device__ float g_rbuf[BB * HH];
__device__ float g_wbuf[BB * LAT];
__device__ float g_w1[BB * LAT];
__device__ float g_alpha[BB * NMATD];
__device__ float g_P[BB * NMATD * LAT];          // 2048 x 2048
__device__ float g_Wstack[256 * 4 * HH];         // permuted [Wx;Wh], cols j*4+gate
__device__ float g_bstack[4 * HH];
__device__ float g_Mbig[272 * NMATD * LAT];      // rows c in [z|u|w], cols i*128+j

// ---------------- weight prep ----------------
__global__ void build_wstack(const float* __restrict__ Wx,
                             const float* __restrict__ Wh,
                             const float* __restrict__ b) {
    int idx = blockIdx.x * blockDim.x + threadIdx.x;
    if (idx < 256 * 512) {
        int row = idx / 512, cp = idx % 512;
        int j = cp >> 2, g = cp & 3;          // permuted col = j*4+g
        int orig = g * 128 + j;               // flax gate order i,f,g,o
        float v = (row < 128) ? Wx[row * 512 + orig] : Wh[(row - 128) * 512 + orig];
        g_Wstack[row * 512 + cp] = v;
    }
    if (idx < 512) {
        int j = idx >> 2, g = idx & 3;
        g_bstack[idx] = b[g * 128 + j];
    }
}

__global__ void build_mbig(const float* __restrict__ A,
                           const float* __restrict__ Bm,
                           const float* __restrict__ C) {
    int idx = blockIdx.x * blockDim.x + threadIdx.x;
    if (idx >= 272 * 2048) return;
    int c = idx / 2048, n = idx % 2048;
    int i = n >> 7, j = n & 127;
    float v;
    if (c < 128)       v = A[i * 128 * 128 + j * 128 + c];
    else if (c < 144)  v = Bm[i * 128 * 16 + j * 16 + (c - 128)];
    else               v = C[i * 128 * 128 + j * 128 + (c - 144)];
    g_Mbig[idx] = v;
}

// ---------------- generic GEMM with 3-way concat A operand ----------------
// out[M,N] = act(cat(s0|s1|s2)[M,K] @ W[K,N] + bias). All widths multiples of 16,
// M multiple of 64, N multiple of 64, K multiple of 16.
template <int ACT, bool BIAS>
__global__ __launch_bounds__(256) void gemm3(
    const float* __restrict__ s0, int w0,
    const float* __restrict__ s1, int w1,
    const float* __restrict__ s2, int w2,
    const float* __restrict__ W, const float* __restrict__ bias,
    float* __restrict__ out, int M, int N, int K) {
    __shared__ float As[16][68];
    __shared__ float Ws[16][64];
    const int tid = threadIdx.x;
    const int m0 = blockIdx.x * 64, n0 = blockIdx.y * 64;
    const int ar = tid >> 2, ac = (tid & 3) << 2;
    const int wr = tid >> 4, wc = (tid & 15) << 2;
    const int tm = (tid >> 4) << 2, tn = (tid & 15) << 2;
    float acc[4][4] = {};
    for (int k0 = 0; k0 < K; k0 += 16) {
        const float* ap; int aw, ak;
        if (k0 < w0)            { ap = s0; aw = w0; ak = k0; }
        else if (k0 < w0 + w1)  { ap = s1; aw = w1; ak = k0 - w0; }
        else                    { ap = s2; aw = w2; ak = k0 - w0 - w1; }
        float4 av = *reinterpret_cast<const float4*>(ap + (size_t)(m0 + ar) * aw + ak + ac);
        As[ac + 0][ar] = av.x; As[ac + 1][ar] = av.y;
        As[ac + 2][ar] = av.z; As[ac + 3][ar] = av.w;
        *reinterpret_cast<float4*>(&Ws[wr][wc]) =
            *reinterpret_cast<const float4*>(W + (size_t)(k0 + wr) * N + n0 + wc);
        __syncthreads();
#pragma unroll
        for (int k = 0; k < 16; k++) {
            float a0 = As[k][tm], a1 = As[k][tm + 1], a2 = As[k][tm + 2], a3 = As[k][tm + 3];
            float4 bv = *reinterpret_cast<float4*>(&Ws[k][tn]);
            acc[0][0] += a0 * bv.x; acc[0][1] += a0 * bv.y; acc[0][2] += a0 * bv.z; acc[0][3] += a0 * bv.w;
            acc[1][0] += a1 * bv.x; acc[1][1] += a1 * bv.y; acc[1][2] += a1 * bv.z; acc[1][3] += a1 * bv.w;
            acc[2][0] += a2 * bv.x; acc[2][1] += a2 * bv.y; acc[2][2] += a2 * bv.z; acc[2][3] += a2 * bv.w;
            acc[3][0] += a3 * bv.x; acc[3][1] += a3 * bv.y; acc[3][2] += a3 * bv.z; acc[3][3] += a3 * bv.w;
        }
        __syncthreads();
    }
#pragma unroll
    for (int i = 0; i < 4; i++) {
        int m = m0 + tm + i;
#pragma unroll
        for (int j = 0; j < 4; j++) {
            int n = n0 + tn + j;
            float v = acc[i][j];
            if (BIAS) v += bias[n];
            if (ACT == 1) v = fmaxf(v, 0.f);
            out[(size_t)m * N + n] = v;
        }
    }
}

// ---------------- gauss GEMM: out = mean + exp(logvar/2)*eps ----------------
// W is K x 256 (first 128 cols mean, last 128 logvar). out is M x 128.
__global__ __launch_bounds__(256) void gemm_gauss(
    const float* __restrict__ Ain, int K,
    const float* __restrict__ W, const float* __restrict__ bias,
    const float* __restrict__ eps, float* __restrict__ out, int M) {
    __shared__ float As[16][68];
    __shared__ float W1s[16][64];
    __shared__ float W2s[16][64];
    const int tid = threadIdx.x;
    const int m0 = blockIdx.x * 64, n0 = blockIdx.y * 64;
    const int ar = tid >> 2, ac = (tid & 3) << 2;
    const int wr = tid >> 4, wc = (tid & 15) << 2;
    const int tm = (tid >> 4) << 2, tn = (tid & 15) << 2;
    float acc1[4][4] = {}, acc2[4][4] = {};
    for (int k0 = 0; k0 < K; k0 += 16) {
        float4 av = *reinterpret_cast<const float4*>(Ain + (size_t)(m0 + ar) * K + k0 + ac);
        As[ac + 0][ar] = av.x; As[ac + 1][ar] = av.y;
        As[ac + 2][ar] = av.z; As[ac + 3][ar] = av.w;
        *reinterpret_cast<float4*>(&W1s[wr][wc]) =
            *reinterpret_cast<const float4*>(W + (size_t)(k0 + wr) * 256 + n0 + wc);
        *reinterpret_cast<float4*>(&W2s[wr][wc]) =
            *reinterpret_cast<const float4*>(W + (size_t)(k0 + wr) * 256 + 128 + n0 + wc);
        __syncthreads();
#pragma unroll
        for (int k = 0; k < 16; k++) {
            float a0 = As[k][tm], a1 = As[k][tm + 1], a2 = As[k][tm + 2], a3 = As[k][tm + 3];
            float4 b1 = *reinterpret_cast<float4*>(&W1s[k][tn]);
            float4 b2 = *reinterpret_cast<float4*>(&W2s[k][tn]);
            acc1[0][0] += a0 * b1.x; acc1[0][1] += a0 * b1.y; acc1[0][2] += a0 * b1.z; acc1[0][3] += a0 * b1.w;
            acc1[1][0] += a1 * b1.x; acc1[1][1] += a1 * b1.y; acc1[1][2] += a1 * b1.z; acc1[1][3] += a1 * b1.w;
            acc1[2][0] += a2 * b1.x; acc1[2][1] += a2 * b1.y; acc1[2][2] += a2 * b1.z; acc1[2][3] += a2 * b1.w;
            acc1[3][0] += a3 * b1.x; acc1[3][1] += a3 * b1.y; acc1[3][2] += a3 * b1.z; acc1[3][3] += a3 * b1.w;
            acc2[0][0] += a0 * b2.x; acc2[0][1] += a0 * b2.y; acc2[0][2] += a0 * b2.z; acc2[0][3] += a0 * b2.w;
            acc2[1][0] += a1 * b2.x; acc2[1][1] += a1 * b2.y; acc2[1][2] += a1 * b2.z; acc2[1][3] += a1 * b2.w;
            acc2[2][0] += a2 * b2.x; acc2[2][1] += a2 * b2.y; acc2[2][2] += a2 * b2.z; acc2[2][3] += a2 * b2.w;
            acc2[3][0] += a3 * b2.x; acc2[3][1] += a3 * b2.y; acc2[3][2] += a3 * b2.z; acc2[3][3] += a3 * b2.w;
        }
        __syncthreads();
    }
#pragma unroll
    for (int i = 0; i < 4; i++) {
        int m = m0 + tm + i;
#pragma unroll
        for (int j = 0; j < 4; j++) {
            int n = n0 + tn + j;
            float mean = acc1[i][j] + bias[n];
            float lv   = acc2[i][j] + bias[128 + n];
            out[(size_t)m * 128 + n] = mean + expf(0.5f * lv) * eps[(size_t)m * 128 + n];
        }
    }
}

// ---------------- LSTM step: gates GEMM + fused cell update ----------------
// A = cat(x_t[128], h_in[128]); W = permuted Wstack (256x512). Each thread's
// 4 cols = (i,f,g,o) of one hidden unit j.
__global__ __launch_bounds__(256) void gemm_lstm(
    const float* __restrict__ x, const float* __restrict__ hin,
    float* __restrict__ c, float* __restrict__ hout) {
    __shared__ float As[16][68];
    __shared__ float Ws[16][64];
    const int tid = threadIdx.x;
    const int m0 = blockIdx.x * 64, n0 = blockIdx.y * 64;
    const int ar = tid >> 2, ac = (tid & 3) << 2;
    const int wr = tid >> 4, wc = (tid & 15) << 2;
    const int tm = (tid >> 4) << 2, tn = (tid & 15) << 2;
    float acc[4][4] = {};
    for (int k0 = 0; k0 < 256; k0 += 16) {
        const float* ap = (k0 < 128) ? x : hin;
        int ak = (k0 < 128) ? k0 : k0 - 128;
        float4 av = *reinterpret_cast<const float4*>(ap + (size_t)(m0 + ar) * 128 + ak + ac);
        As[ac + 0][ar] = av.x; As[ac + 1][ar] = av.y;
        As[ac + 2][ar] = av.z; As[ac + 3][ar] = av.w;
        *reinterpret_cast<float4*>(&Ws[wr][wc]) =
            *reinterpret_cast<const float4*>(g_Wstack + (size_t)(k0 + wr) * 512 + n0 + wc);
        __syncthreads();
#pragma unroll
        for (int k = 0; k < 16; k++) {
            float a0 = As[k][tm], a1 = As[k][tm + 1], a2 = As[k][tm + 2], a3 = As[k][tm + 3];
            float4 bv = *reinterpret_cast<float4*>(&Ws[k][tn]);
            acc[0][0] += a0 * bv.x; acc[0][1] += a0 * bv.y; acc[0][2] += a0 * bv.z; acc[0][3] += a0 * bv.w;
            acc[1][0] += a1 * bv.x; acc[1][1] += a1 * bv.y; acc[1][2] += a1 * bv.z; acc[1][3] += a1 * bv.w;
            acc[2][0] += a2 * bv.x; acc[2][1] += a2 * bv.y; acc[2][2] += a2 * bv.z; acc[2][3] += a2 * bv.w;
            acc[3][0] += a3 * bv.x; acc[3][1] += a3 * bv.y; acc[3][2] += a3 * bv.z; acc[3][3] += a3 * bv.w;
        }
        __syncthreads();
    }
    const int j = (n0 + tn) >> 2;
    float b0 = g_bstack[n0 + tn + 0], b1 = g_bstack[n0 + tn + 1];
    float b2 = g_bstack[n0 + tn + 2], b3 = g_bstack[n0 + tn + 3];
#pragma unroll
    for (int i = 0; i < 4; i++) {
        int b = m0 + tm + i;
        float gi = acc[i][0] + b0;
        float gf = acc[i][1] + b1;
        float gg = acc[i][2] + b2;
        float go = acc[i][3] + b3;
        float si = 1.f / (1.f + expf(-gi));
        float sf = 1.f / (1.f + expf(-gf));
        float so = 1.f / (1.f + expf(-go));
        size_t idx = (size_t)b * 128 + j;
        float cn = sf * c[idx] + si * tanhf(gg);
        c[idx] = cn;
        hout[idx] = so * tanhf(cn);
    }
}

// ---------------- alpha logits + softmax (N=16) ----------------
__global__ __launch_bounds__(256) void alpha_kernel(
    const float* __restrict__ z, const float* __restrict__ u,
    const float* __restrict__ aW, float* __restrict__ alpha) {
    __shared__ float sW[144][16];
    __shared__ float sl[16][16];
    __shared__ float se[16][16];
    const int tid = threadIdx.x;
    for (int idx = tid; idx < 144 * 16; idx += 256)
        sW[idx / 16][idx % 16] = aW[idx];
    __syncthreads();
    const int br = tid >> 4, i = tid & 15;
    const int b = blockIdx.x * 16 + br;
    const float* zb = z + (size_t)b * 128;
    const float* ub = u + (size_t)b * 16;
    float acc = 0.f;
#pragma unroll 8
    for (int k = 0; k < 128; k++) acc += zb[k] * sW[k][i];
#pragma unroll
    for (int k = 0; k < 16; k++) acc += ub[k] * sW[128 + k][i];
    sl[br][i] = acc;
    __syncthreads();
    float mx = -1e30f;
#pragma unroll
    for (int q = 0; q < 16; q++) mx = fmaxf(mx, sl[br][q]);
    float e = expf(acc - mx);
    se[br][i] = e;
    __syncthreads();
    float s = 0.f;
#pragma unroll
    for (int q = 0; q < 16; q++) s += se[br][q];
    alpha[(size_t)b * 16 + i] = e / s;
}

// ---------------- z_next = sum_i alpha[b,i] * P[b, i*128+j] ----------------
__global__ __launch_bounds__(256) void mix_reduce(
    const float* __restrict__ P, const float* __restrict__ alpha,
    float* __restrict__ znext) {
    int idx = blockIdx.x * 256 + threadIdx.x;   // B*128 total
    int b = idx >> 7, j = idx & 127;
    const float* pb = P + (size_t)b * 2048 + j;
    const float* ab = alpha + (size_t)b * 16;
    float s = 0.f;
#pragma unroll
    for (int i = 0; i < 16; i++) s += ab[i] * pb[i * 128];
    znext[idx] = s;
}

// ---------------- host orchestration ----------------
extern "C" void kernel_launch(void* const* d_in, const int* in_sizes, int n_in,
                              void* d_out, int out_size) {
    const float* xs      = (const float*)d_in[0];
    const float* us      = (const float*)d_in[1];
    const float* eps1    = (const float*)d_in[2];
    const float* eps     = (const float*)d_in[3];
    const float* lstm_Wx = (const float*)d_in[4];
    const float* lstm_Wh = (const float*)d_in[5];
    const float* lstm_b  = (const float*)d_in[6];
    const float* init_W1 = (const float*)d_in[7];
    const float* init_b1 = (const float*)d_in[8];
    const float* init_W2 = (const float*)d_in[9];
    const float* init_b2 = (const float*)d_in[10];
    const float* trans_W1= (const float*)d_in[11];
    const float* trans_b1= (const float*)d_in[12];
    const float* trans_W2= (const float*)d_in[13];
    const float* trans_b2= (const float*)d_in[14];
    const float* obs_W1  = (const float*)d_in[15];
    const float* obs_b1  = (const float*)d_in[16];
    const float* obs_W2  = (const float*)d_in[17];
    const float* obs_b2  = (const float*)d_in[18];
    const float* rec_W1  = (const float*)d_in[19];
    const float* rec_b1  = (const float*)d_in[20];
    const float* rec_W2  = (const float*)d_in[21];
    const float* rec_b2  = (const float*)d_in[22];
    const float* alpha_W = (const float*)d_in[23];
    const float* Abank   = (const float*)d_in[24];
    const float* Bbank   = (const float*)d_in[25];
    const float* Cbank   = (const float*)d_in[26];

    float *h0, *h1, *c, *hbuf, *rbuf, *wbuf, *w1buf, *alphaB, *P, *Mbig;
    cudaGetSymbolAddress((void**)&h0, g_h0);
    cudaGetSymbolAddress((void**)&h1, g_h1);
    cudaGetSymbolAddress((void**)&c, g_c);
    cudaGetSymbolAddress((void**)&hbuf, g_hbuf);
    cudaGetSymbolAddress((void**)&rbuf, g_rbuf);
    cudaGetSymbolAddress((void**)&wbuf, g_wbuf);
    cudaGetSymbolAddress((void**)&w1buf, g_w1);
    cudaGetSymbolAddress((void**)&alphaB, g_alpha);
    cudaGetSymbolAddress((void**)&P, g_P);
    cudaGetSymbolAddress((void**)&Mbig, g_Mbig);

    cudaMemsetAsync(h0, 0, sizeof(float) * BB * HH);
    cudaMemsetAsync(c, 0, sizeof(float) * BB * HH);

    build_wstack<<<(256 * 512 + 255) / 256, 256>>>(lstm_Wx, lstm_Wh, lstm_b);
    build_mbig<<<(272 * 2048 + 255) / 256, 256>>>(Abank, Bbank, Cbank);

    // LSTM over T (ping-pong h)
    dim3 gLSTM(BB / 64, 512 / 64);
    for (int t = 0; t < TT; t++) {
        const float* hin = (t & 1) ? h1 : h0;
        float* hout      = (t & 1) ? h0 : h1;
        gemm_lstm<<<gLSTM, 256>>>(xs + (size_t)t * BB * OBSD, hin, c, hout);
    }
    float* hfin = h0;  // t=63 (odd) wrote h0

    float* zs   = (float*)d_out;
    float* xrec = zs + (size_t)TT * BB * LAT;

    dim3 g128(BB / 64, 2);
    // init network
    gemm3<1, true><<<g128, 256>>>(hfin, 128, nullptr, 0, nullptr, 0,
                                  init_W1, init_b1, hbuf, BB, 128, 128);
    gemm_gauss<<<g128, 256>>>(hbuf, 128, init_W2, init_b2, eps1, w1buf, BB);
    gemm3<1, true><<<g128, 256>>>(w1buf, 128, nullptr, 0, nullptr, 0,
                                  trans_W1, trans_b1, hbuf, BB, 128, 128);
    gemm3<0, true><<<g128, 256>>>(hbuf, 128, nullptr, 0, nullptr, 0,
                                  trans_W2, trans_b2, zs, BB, 128, 128);

    dim3 gMix(BB / 64, 2048 / 64);
    for (int t = 0; t < TT - 1; t++) {
        const float* z  = zs + (size_t)t * BB * LAT;
        float* zn       = zs + (size_t)(t + 1) * BB * LAT;
        float* xr       = xrec + (size_t)t * BB * OBSD;
        const float* xt1 = xs + (size_t)(t + 1) * BB * OBSD;
        const float* ut  = us + (size_t)t * BB * CTRL;
        // observation: x_mean from current z
        gemm3<1, true><<<g128, 256>>>(z, 128, nullptr, 0, nullptr, 0,
                                      obs_W1, obs_b1, hbuf, BB, 128, 128);
        gemm3<0, true><<<g128, 256>>>(hbuf, 128, nullptr, 0, nullptr, 0,
                                      obs_W2, obs_b2, xr, BB, 128, 128);
        // recognition: r = relu([z,x_next,u] @ rec_W1 + b1); w = mean+exp(lv/2)*eps
        gemm3<1, true><<<g128, 256>>>(z, 128, xt1, 128, ut, 16,
                                      rec_W1, rec_b1, rbuf, BB, 128, 272);
        gemm_gauss<<<g128, 256>>>(rbuf, 128, rec_W2, rec_b2,
                                  eps + (size_t)t * BB * LAT, wbuf, BB);
        // alphas
        alpha_kernel<<<BB / 16, 256>>>(z, ut, alpha_W, alphaB);
        // P = [z,u,w] @ Mbig ; z_next = alpha-weighted reduce
        gemm3<0, false><<<gMix, 256>>>(z, 128, ut, 16, wbuf, 128,
                                       Mbig, nullptr, P, BB, 2048, 272);
        mix_reduce<<<BB * 128 / 256, 256>>>(P, alphaB, zn);
    }
}

// round 4
// speedup vs baseline: 1.5817x; 1.5817x over previous
#include <cuda_runtime.h>
#include <math.h>

#define TT    64
#define BB    2048
#define LAT   128
#define OBSD  128
#define CTRL  16
#define NMATD 16
#define HH    128

// ---------------- scratch (no allocation allowed) ----------------
__device__ float g_h0[BB * HH];
__device__ float g_h1[BB * HH];
__device__ float g_c[BB * HH];
__device__ float g_hbuf[BB * HH];
__device__ float g_rbuf[BB * HH];
__device__ float g_wbuf[BB * LAT];
__device__ float g_w1[BB * LAT];
__device__ float g_alpha[BB * NMATD];
__device__ float g_P[BB * NMATD * LAT];       // 2048 x 2048
__device__ float g_Wstack[256 * 512];         // LSTM weights, gate-permuted cols
__device__ float g_bstack[512];
__device__ float g_Mbig[272 * NMATD * LAT];   // rows c in [z|u|w], cols i*128+j
__device__ float g_W2il_init[128 * 256];      // interleaved (mean,logvar) cols
__device__ float g_W2il_rec[128 * 256];
__device__ float g_b2il_init[256];
__device__ float g_b2il_rec[256];

// ---------------- helpers ----------------
__device__ __forceinline__ float tf32r(float x) {
    unsigned u;
    asm("cvt.rna.tf32.f32 %0, %1;" : "=r"(u) : "f"(x));
    return __uint_as_float(u);
}

__device__ __forceinline__ void mma8(float (&c)[4], const float (&a)[4],
                                     const float (&b)[2]) {
    asm volatile(
        "mma.sync.aligned.m16n8k8.row.col.f32.tf32.tf32.f32 "
        "{%0,%1,%2,%3}, {%4,%5,%6,%7}, {%8,%9}, {%0,%1,%2,%3};\n"
        : "+f"(c[0]), "+f"(c[1]), "+f"(c[2]), "+f"(c[3])
        : "r"(__float_as_uint(a[0])), "r"(__float_as_uint(a[1])),
          "r"(__float_as_uint(a[2])), "r"(__float_as_uint(a[3])),
          "r"(__float_as_uint(b[0])), "r"(__float_as_uint(b[1])));
}

// ---------------- weight prep ----------------
// LSTM cols permuted: cp = (j>>3)*32 + gate*8 + (j&7); flax order i,f,g,o.
__global__ void build_wstack(const float* __restrict__ Wx,
                             const float* __restrict__ Wh,
                             const float* __restrict__ b) {
    int idx = blockIdx.x * blockDim.x + threadIdx.x;
    if (idx < 256 * 512) {
        int row = idx / 512, cp = idx % 512;
        int gate = (cp >> 3) & 3;
        int j = (cp >> 5) * 8 + (cp & 7);
        int orig = gate * 128 + j;
        float v = (row < 128) ? Wx[row * 512 + orig] : Wh[(row - 128) * 512 + orig];
        g_Wstack[row * 512 + cp] = v;
    }
    if (idx < 512) {
        int gate = (idx >> 3) & 3;
        int j = (idx >> 5) * 8 + (idx & 7);
        g_bstack[idx] = b[gate * 128 + j];
    }
}

__global__ void build_mbig(const float* __restrict__ A,
                           const float* __restrict__ Bm,
                           const float* __restrict__ C) {
    int idx = blockIdx.x * blockDim.x + threadIdx.x;
    if (idx >= 272 * 2048) return;
    int c = idx / 2048, n = idx % 2048;
    int i = n >> 7, j = n & 127;
    float v;
    if (c < 128)       v = A[i * 128 * 128 + j * 128 + c];
    else if (c < 144)  v = Bm[i * 128 * 16 + j * 16 + (c - 128)];
    else               v = C[i * 128 * 128 + j * 128 + (c - 144)];
    g_Mbig[idx] = v;
}

// interleave (mean, logvar) columns: Wil[k][2j]=W[k][j], Wil[k][2j+1]=W[k][128+j]
__global__ void build_w2il(const float* __restrict__ W, const float* __restrict__ b,
                           float* __restrict__ Wil, float* __restrict__ bil) {
    int idx = blockIdx.x * blockDim.x + threadIdx.x;
    if (idx < 128 * 256) {
        int k = idx / 256, cp = idx % 256;
        Wil[idx] = W[k * 256 + (cp & 1) * 128 + (cp >> 1)];
    }
    if (idx < 256) bil[idx] = b[(idx & 1) * 128 + (idx >> 1)];
}

// ---------------- tf32 tensor GEMM, CTA 128x128, cat3 A operand ----------------
// ACT: 0 none, 1 relu, 2 gauss (W interleaved, N=256, out = mean+exp(lv/2)*eps,
// out row stride 128). M,N multiples of 128; w0,w1,w2,K multiples of 16.
template <int ACT, bool BIAS>
__global__ __launch_bounds__(256) void tmm(
    const float* __restrict__ s0, int w0,
    const float* __restrict__ s1, int w1,
    const float* __restrict__ s2, int w2,
    const float* __restrict__ W, const float* __restrict__ bias,
    const float* __restrict__ eps,
    float* __restrict__ out, int M, int N, int K) {
    __shared__ float As[16][136];
    __shared__ float Bs[16][136];
    const int tid = threadIdx.x;
    const int lane = tid & 31, warp = tid >> 5;
    const int m0 = blockIdx.x * 128, n0 = blockIdx.y * 128;
    const int wm = (warp >> 2) * 64, wn = (warp & 3) * 32;
    const int g = lane >> 2, tg = lane & 3;
    float acc[4][4][4];
#pragma unroll
    for (int i = 0; i < 4; i++)
#pragma unroll
        for (int j = 0; j < 4; j++)
#pragma unroll
            for (int q = 0; q < 4; q++) acc[i][j][q] = 0.f;

    const int nch = K >> 4;
    float4 pa[2], pb[2];

    auto gload = [&](int ch) {
        int kb = ch << 4;
        const float* sp; int sw;
        if (kb < w0)           { sp = s0 + kb;           sw = w0; }
        else if (kb < w0 + w1) { sp = s1 + (kb - w0);     sw = w1; }
        else                   { sp = s2 + (kb - w0 - w1); sw = w2; }
#pragma unroll
        for (int i = 0; i < 2; i++) {
            int idx = tid + (i << 8);
            int r = idx >> 2, c4 = (idx & 3) << 2;
            pa[i] = *(const float4*)(sp + (size_t)(m0 + r) * sw + c4);
            int br = idx >> 5, bc4 = (idx & 31) << 2;
            pb[i] = *(const float4*)(W + (size_t)(kb + br) * N + n0 + bc4);
        }
    };
    auto sstore = [&]() {
#pragma unroll
        for (int i = 0; i < 2; i++) {
            int idx = tid + (i << 8);
            int r = idx >> 2, c4 = (idx & 3) << 2;
            As[c4 + 0][r] = tf32r(pa[i].x); As[c4 + 1][r] = tf32r(pa[i].y);
            As[c4 + 2][r] = tf32r(pa[i].z); As[c4 + 3][r] = tf32r(pa[i].w);
            int br = idx >> 5, bc4 = (idx & 31) << 2;
            float4 t;
            t.x = tf32r(pb[i].x); t.y = tf32r(pb[i].y);
            t.z = tf32r(pb[i].z); t.w = tf32r(pb[i].w);
            *(float4*)&Bs[br][bc4] = t;
        }
    };

    gload(0);
    for (int ch = 0; ch < nch; ch++) {
        __syncthreads();
        sstore();
        __syncthreads();
        if (ch + 1 < nch) gload(ch + 1);
#pragma unroll
        for (int kk = 0; kk < 16; kk += 8) {
            float a[4][4], b[4][2];
#pragma unroll
            for (int mt = 0; mt < 4; mt++) {
                int r = wm + mt * 16 + g;
                a[mt][0] = As[kk + tg][r];
                a[mt][1] = As[kk + tg][r + 8];
                a[mt][2] = As[kk + tg + 4][r];
                a[mt][3] = As[kk + tg + 4][r + 8];
            }
#pragma unroll
            for (int nt = 0; nt < 4; nt++) {
                int c = wn + nt * 8 + g;
                b[nt][0] = Bs[kk + tg][c];
                b[nt][1] = Bs[kk + tg + 4][c];
            }
#pragma unroll
            for (int mt = 0; mt < 4; mt++)
#pragma unroll
                for (int nt = 0; nt < 4; nt++)
                    mma8(acc[mt][nt], a[mt], b[nt]);
        }
    }

#pragma unroll
    for (int mt = 0; mt < 4; mt++) {
#pragma unroll
        for (int nt = 0; nt < 4; nt++) {
            int r = m0 + wm + mt * 16 + g;
            int c = n0 + wn + nt * 8 + 2 * tg;
            if (ACT == 2) {
                int j = c >> 1;
                float bm = bias[c], bl = bias[c + 1];
                float mean0 = acc[mt][nt][0] + bm, lv0 = acc[mt][nt][1] + bl;
                float mean1 = acc[mt][nt][2] + bm, lv1 = acc[mt][nt][3] + bl;
                out[(size_t)r * 128 + j] =
                    mean0 + expf(0.5f * lv0) * eps[(size_t)r * 128 + j];
                out[(size_t)(r + 8) * 128 + j] =
                    mean1 + expf(0.5f * lv1) * eps[(size_t)(r + 8) * 128 + j];
            } else {
                float2 v0 = make_float2(acc[mt][nt][0], acc[mt][nt][1]);
                float2 v1 = make_float2(acc[mt][nt][2], acc[mt][nt][3]);
                if (BIAS) {
                    float bx = bias[c], by = bias[c + 1];
                    v0.x += bx; v0.y += by; v1.x += bx; v1.y += by;
                }
                if (ACT == 1) {
                    v0.x = fmaxf(v0.x, 0.f); v0.y = fmaxf(v0.y, 0.f);
                    v1.x = fmaxf(v1.x, 0.f); v1.y = fmaxf(v1.y, 0.f);
                }
                *(float2*)(out + (size_t)r * N + c) = v0;
                *(float2*)(out + (size_t)(r + 8) * N + c) = v1;
            }
        }
    }
}

// ---------------- fused tf32 LSTM step ----------------
// gates = [x|h] @ Wstack (gate-permuted, 256x512); each thread's 4 n-subtiles
// are the 4 gates of its 2 units -> cell update in epilogue.
__global__ __launch_bounds__(256) void lstm_step(
    const float* __restrict__ x, const float* __restrict__ hin,
    float* __restrict__ c, float* __restrict__ hout) {
    __shared__ float As[16][136];
    __shared__ float Bs[16][136];
    const int tid = threadIdx.x;
    const int lane = tid & 31, warp = tid >> 5;
    const int m0 = blockIdx.x * 128, n0 = blockIdx.y * 128;
    const int wm = (warp >> 2) * 64, wn = (warp & 3) * 32;
    const int g = lane >> 2, tg = lane & 3;
    float acc[4][4][4];
#pragma unroll
    for (int i = 0; i < 4; i++)
#pragma unroll
        for (int j = 0; j < 4; j++)
#pragma unroll
            for (int q = 0; q < 4; q++) acc[i][j][q] = 0.f;

    float4 pa[2], pb[2];
    auto gload = [&](int ch) {
        int kb = ch << 4;
        const float* sp = (kb < 128) ? (x + kb) : (hin + kb - 128);
#pragma unroll
        for (int i = 0; i < 2; i++) {
            int idx = tid + (i << 8);
            int r = idx >> 2, c4 = (idx & 3) << 2;
            pa[i] = *(const float4*)(sp + (size_t)(m0 + r) * 128 + c4);
            int br = idx >> 5, bc4 = (idx & 31) << 2;
            pb[i] = *(const float4*)(g_Wstack + (size_t)(kb + br) * 512 + n0 + bc4);
        }
    };
    auto sstore = [&]() {
#pragma unroll
        for (int i = 0; i < 2; i++) {
            int idx = tid + (i << 8);
            int r = idx >> 2, c4 = (idx & 3) << 2;
            As[c4 + 0][r] = tf32r(pa[i].x); As[c4 + 1][r] = tf32r(pa[i].y);
            As[c4 + 2][r] = tf32r(pa[i].z); As[c4 + 3][r] = tf32r(pa[i].w);
            int br = idx >> 5, bc4 = (idx & 31) << 2;
            float4 t;
            t.x = tf32r(pb[i].x); t.y = tf32r(pb[i].y);
            t.z = tf32r(pb[i].z); t.w = tf32r(pb[i].w);
            *(float4*)&Bs[br][bc4] = t;
        }
    };

    gload(0);
    for (int ch = 0; ch < 16; ch++) {
        __syncthreads();
        sstore();
        __syncthreads();
        if (ch + 1 < 16) gload(ch + 1);
#pragma unroll
        for (int kk = 0; kk < 16; kk += 8) {
            float a[4][4], b[4][2];
#pragma unroll
            for (int mt = 0; mt < 4; mt++) {
                int r = wm + mt * 16 + g;
                a[mt][0] = As[kk + tg][r];
                a[mt][1] = As[kk + tg][r + 8];
                a[mt][2] = As[kk + tg + 4][r];
                a[mt][3] = As[kk + tg + 4][r + 8];
            }
#pragma unroll
            for (int nt = 0; nt < 4; nt++) {
                int cc = wn + nt * 8 + g;
                b[nt][0] = Bs[kk + tg][cc];
                b[nt][1] = Bs[kk + tg + 4][cc];
            }
#pragma unroll
            for (int mt = 0; mt < 4; mt++)
#pragma unroll
                for (int nt = 0; nt < 4; nt++)
                    mma8(acc[mt][nt], a[mt], b[nt]);
        }
    }

    const int jbase = ((n0 + wn) >> 5) * 8 + 2 * tg;
    float bs[4][2];
#pragma unroll
    for (int nt = 0; nt < 4; nt++) {
        bs[nt][0] = g_bstack[n0 + wn + nt * 8 + 2 * tg];
        bs[nt][1] = g_bstack[n0 + wn + nt * 8 + 2 * tg + 1];
    }
#pragma unroll
    for (int mt = 0; mt < 4; mt++) {
#pragma unroll
        for (int half = 0; half < 2; half++) {
            int row = m0 + wm + mt * 16 + g + half * 8;
#pragma unroll
            for (int b = 0; b < 2; b++) {
                int q = half * 2 + b;
                float gi = acc[mt][0][q] + bs[0][b];
                float gf = acc[mt][1][q] + bs[1][b];
                float gg = acc[mt][2][q] + bs[2][b];
                float go = acc[mt][3][q] + bs[3][b];
                float si = 1.f / (1.f + expf(-gi));
                float sf = 1.f / (1.f + expf(-gf));
                float so = 1.f / (1.f + expf(-go));
                size_t idx = (size_t)row * 128 + jbase + b;
                float cn = sf * c[idx] + si * tanhf(gg);
                c[idx] = cn;
                hout[idx] = so * tanhf(cn);
            }
        }
    }
}

// ---------------- alpha logits + softmax (N=16) ----------------
__global__ __launch_bounds__(256) void alpha_kernel(
    const float* __restrict__ z, const float* __restrict__ u,
    const float* __restrict__ aW, float* __restrict__ alpha) {
    __shared__ float sW[144][16];
    __shared__ float sl[16][16];
    __shared__ float se[16][16];
    const int tid = threadIdx.x;
    for (int idx = tid; idx < 144 * 16; idx += 256)
        sW[idx / 16][idx % 16] = aW[idx];
    __syncthreads();
    const int br = tid >> 4, i = tid & 15;
    const int b = blockIdx.x * 16 + br;
    const float* zb = z + (size_t)b * 128;
    const float* ub = u + (size_t)b * 16;
    float acc = 0.f;
#pragma unroll 8
    for (int k = 0; k < 128; k++) acc += zb[k] * sW[k][i];
#pragma unroll
    for (int k = 0; k < 16; k++) acc += ub[k] * sW[128 + k][i];
    sl[br][i] = acc;
    __syncthreads();
    float mx = -1e30f;
#pragma unroll
    for (int q = 0; q < 16; q++) mx = fmaxf(mx, sl[br][q]);
    float e = expf(acc - mx);
    se[br][i] = e;
    __syncthreads();
    float s = 0.f;
#pragma unroll
    for (int q = 0; q < 16; q++) s += se[br][q];
    alpha[(size_t)b * 16 + i] = e / s;
}

// ---------------- z_next = sum_i alpha[b,i] * P[b, i*128+j] ----------------
__global__ __launch_bounds__(256) void mix_reduce(
    const float* __restrict__ P, const float* __restrict__ alpha,
    float* __restrict__ znext) {
    int idx = blockIdx.x * 256 + threadIdx.x;
    int b = idx >> 7, j = idx & 127;
    const float* pb = P + (size_t)b * 2048 + j;
    const float* ab = alpha + (size_t)b * 16;
    float s = 0.f;
#pragma unroll
    for (int i = 0; i < 16; i++) s += ab[i] * pb[i * 128];
    znext[idx] = s;
}

// ---------------- host orchestration ----------------
extern "C" void kernel_launch(void* const* d_in, const int* in_sizes, int n_in,
                              void* d_out, int out_size) {
    const float* xs      = (const float*)d_in[0];
    const float* us      = (const float*)d_in[1];
    const float* eps1    = (const float*)d_in[2];
    const float* eps     = (const float*)d_in[3];
    const float* lstm_Wx = (const float*)d_in[4];
    const float* lstm_Wh = (const float*)d_in[5];
    const float* lstm_b  = (const float*)d_in[6];
    const float* init_W1 = (const float*)d_in[7];
    const float* init_b1 = (const float*)d_in[8];
    const float* init_W2 = (const float*)d_in[9];
    const float* init_b2 = (const float*)d_in[10];
    const float* trans_W1= (const float*)d_in[11];
    const float* trans_b1= (const float*)d_in[12];
    const float* trans_W2= (const float*)d_in[13];
    const float* trans_b2= (const float*)d_in[14];
    const float* obs_W1  = (const float*)d_in[15];
    const float* obs_b1  = (const float*)d_in[16];
    const float* obs_W2  = (const float*)d_in[17];
    const float* obs_b2  = (const float*)d_in[18];
    const float* rec_W1  = (const float*)d_in[19];
    const float* rec_b1  = (const float*)d_in[20];
    const float* rec_W2  = (const float*)d_in[21];
    const float* rec_b2  = (const float*)d_in[22];
    const float* alpha_W = (const float*)d_in[23];
    const float* Abank   = (const float*)d_in[24];
    const float* Bbank   = (const float*)d_in[25];
    const float* Cbank   = (const float*)d_in[26];

    float *h0, *h1, *c, *hbuf, *rbuf, *wbuf, *w1buf, *alphaB, *P, *Mbig;
    float *Wil_i, *Wil_r, *bil_i, *bil_r;
    cudaGetSymbolAddress((void**)&h0, g_h0);
    cudaGetSymbolAddress((void**)&h1, g_h1);
    cudaGetSymbolAddress((void**)&c, g_c);
    cudaGetSymbolAddress((void**)&hbuf, g_hbuf);
    cudaGetSymbolAddress((void**)&rbuf, g_rbuf);
    cudaGetSymbolAddress((void**)&wbuf, g_wbuf);
    cudaGetSymbolAddress((void**)&w1buf, g_w1);
    cudaGetSymbolAddress((void**)&alphaB, g_alpha);
    cudaGetSymbolAddress((void**)&P, g_P);
    cudaGetSymbolAddress((void**)&Mbig, g_Mbig);
    cudaGetSymbolAddress((void**)&Wil_i, g_W2il_init);
    cudaGetSymbolAddress((void**)&Wil_r, g_W2il_rec);
    cudaGetSymbolAddress((void**)&bil_i, g_b2il_init);
    cudaGetSymbolAddress((void**)&bil_r, g_b2il_rec);

    cudaMemsetAsync(h0, 0, sizeof(float) * BB * HH);
    cudaMemsetAsync(c, 0, sizeof(float) * BB * HH);

    build_wstack<<<(256 * 512 + 255) / 256, 256>>>(lstm_Wx, lstm_Wh, lstm_b);
    build_mbig<<<(272 * 2048 + 255) / 256, 256>>>(Abank, Bbank, Cbank);
    build_w2il<<<(128 * 256 + 255) / 256, 256>>>(init_W2, init_b2, Wil_i, bil_i);
    build_w2il<<<(128 * 256 + 255) / 256, 256>>>(rec_W2, rec_b2, Wil_r, bil_r);

    // LSTM over T (ping-pong h)
    dim3 gLSTM(BB / 128, 512 / 128);
    for (int t = 0; t < TT; t++) {
        const float* hin = (t & 1) ? h1 : h0;
        float* hout      = (t & 1) ? h0 : h1;
        lstm_step<<<gLSTM, 256>>>(xs + (size_t)t * BB * OBSD, hin, c, hout);
    }
    float* hfin = h0;  // t=63 (odd) wrote h0

    float* zs   = (float*)d_out;
    float* xrec = zs + (size_t)TT * BB * LAT;

    dim3 g1(BB / 128, 1), g2(BB / 128, 2), gMix(BB / 128, 2048 / 128);
    // init network
    tmm<1, true><<<g1, 256>>>(hfin, 128, nullptr, 0, nullptr, 0,
                              init_W1, init_b1, nullptr, hbuf, BB, 128, 128);
    tmm<2, true><<<g2, 256>>>(hbuf, 128, nullptr, 0, nullptr, 0,
                              Wil_i, bil_i, eps1, w1buf, BB, 256, 128);
    tmm<1, true><<<g1, 256>>>(w1buf, 128, nullptr, 0, nullptr, 0,
                              trans_W1, trans_b1, nullptr, hbuf, BB, 128, 128);
    tmm<0, true><<<g1, 256>>>(hbuf, 128, nullptr, 0, nullptr, 0,
                              trans_W2, trans_b2, nullptr, zs, BB, 128, 128);

    for (int t = 0; t < TT - 1; t++) {
        const float* z   = zs + (size_t)t * BB * LAT;
        float* zn        = zs + (size_t)(t + 1) * BB * LAT;
        float* xr        = xrec + (size_t)t * BB * OBSD;
        const float* xt1 = xs + (size_t)(t + 1) * BB * OBSD;
        const float* ut  = us + (size_t)t * BB * CTRL;
        // observation
        tmm<1, true><<<g1, 256>>>(z, 128, nullptr, 0, nullptr, 0,
                                  obs_W1, obs_b1, nullptr, hbuf, BB, 128, 128);
        tmm<0, true><<<g1, 256>>>(hbuf, 128, nullptr, 0, nullptr, 0,
                                  obs_W2, obs_b2, nullptr, xr, BB, 128, 128);
        // recognition + gauss sample
        tmm<1, true><<<g1, 256>>>(z, 128, xt1, 128, ut, 16,
                                  rec_W1, rec_b1, nullptr, rbuf, BB, 128, 272);
        tmm<2, true><<<g2, 256>>>(rbuf, 128, nullptr, 0, nullptr, 0,
                                  Wil_r, bil_r, eps + (size_t)t * BB * LAT,
                                  wbuf, BB, 256, 128);
        // alphas
        alpha_kernel<<<BB / 16, 256>>>(z, ut, alpha_W, alphaB);
        // P = [z,u,w] @ Mbig ; z_next = alpha-weighted reduce
        tmm<0, false><<<gMix, 256>>>(z, 128, ut, 16, wbuf, 128,
                                     Mbig, nullptr, nullptr, P, BB, 2048, 272);
        mix_reduce<<<BB * 128 / 256, 256>>>(P, alphaB, zn);
    }
}

// round 7
// speedup vs baseline: 2.0502x; 1.2962x over previous
#include <cuda_runtime.h>
#include <math.h>

#define TT    64
#define BB    2048
#define LAT   128
#define OBSD  128
#define CTRL  16
#define NMATD 16
#define HH    128
#define TM1   (TT - 1)

// ---------------- scratch (no allocation allowed) ----------------
__device__ float g_h0[BB * HH];
__device__ float g_h1[BB * HH];
__device__ float g_c[BB * HH];
__device__ float g_hbuf[BB * HH];
__device__ float g_rbuf[BB * HH];
__device__ float g_wbuf[BB * LAT];
__device__ float g_w1[BB * LAT];
__device__ float g_P[BB * NMATD * LAT];         // 2048 x 2048
__device__ float g_WxP[128 * 512];              // permuted LSTM x-weights
__device__ float g_WhP[128 * 512];              // permuted LSTM h-weights
__device__ float g_bstack[512];
__device__ float g_Mbig[272 * NMATD * LAT];     // rows c in [z|u|w], cols i*128+j
__device__ float g_W2il_init[128 * 256];        // interleaved (mean,logvar) cols
__device__ float g_W2il_rec[128 * 256];
__device__ float g_b2il_init[256];
__device__ float g_b2il_rec[256];
__device__ float g_Gx[TT * BB * 512];           // batched x@WxP for all t
__device__ float g_Rxu[TM1 * BB * HH];          // [x_{t+1}|u_t]@recW1[128:]+b1
__device__ float g_alphau[TM1 * BB * NMATD];    // u_t part of alpha logits
__device__ float g_Hobs[TM1 * BB * HH];         // batched obs hidden

// ---------------- helpers ----------------
__device__ __forceinline__ float tf32r(float x) {
    unsigned u;
    asm("cvt.rna.tf32.f32 %0, %1;" : "=r"(u) : "f"(x));
    return __uint_as_float(u);
}

__device__ __forceinline__ void mma8(float (&c)[4], const float (&a)[4],
                                     const float (&b)[2]) {
    asm volatile(
        "mma.sync.aligned.m16n8k8.row.col.f32.tf32.tf32.f32 "
        "{%0,%1,%2,%3}, {%4,%5,%6,%7}, {%8,%9}, {%0,%1,%2,%3};\n"
        : "+f"(c[0]), "+f"(c[1]), "+f"(c[2]), "+f"(c[3])
        : "r"(__float_as_uint(a[0])), "r"(__float_as_uint(a[1])),
          "r"(__float_as_uint(a[2])), "r"(__float_as_uint(a[3])),
          "r"(__float_as_uint(b[0])), "r"(__float_as_uint(b[1])));
}

// ---------------- weight prep ----------------
// LSTM cols permuted: cp = (j>>3)*32 + gate*8 + (j&7); flax gate order i,f,g,o.
__global__ void build_wstack(const float* __restrict__ Wx,
                             const float* __restrict__ Wh,
                             const float* __restrict__ b) {
    int idx = blockIdx.x * blockDim.x + threadIdx.x;
    if (idx < 128 * 512) {
        int row = idx / 512, cp = idx % 512;
        int gate = (cp >> 3) & 3;
        int j = (cp >> 5) * 8 + (cp & 7);
        int orig = gate * 128 + j;
        g_WxP[idx] = Wx[row * 512 + orig];
        g_WhP[idx] = Wh[row * 512 + orig];
    }
    if (idx < 512) {
        int gate = (idx >> 3) & 3;
        int j = (idx >> 5) * 8 + (idx & 7);
        g_bstack[idx] = b[gate * 128 + j];
    }
}

__global__ void build_mbig(const float* __restrict__ A,
                           const float* __restrict__ Bm,
                           const float* __restrict__ C) {
    int idx = blockIdx.x * blockDim.x + threadIdx.x;
    if (idx >= 272 * 2048) return;
    int c = idx / 2048, n = idx % 2048;
    int i = n >> 7, j = n & 127;
    float v;
    if (c < 128)       v = A[i * 128 * 128 + j * 128 + c];
    else if (c < 144)  v = Bm[i * 128 * 16 + j * 16 + (c - 128)];
    else               v = C[i * 128 * 128 + j * 128 + (c - 144)];
    g_Mbig[idx] = v;
}

__global__ void build_w2il(const float* __restrict__ W, const float* __restrict__ b,
                           float* __restrict__ Wil, float* __restrict__ bil) {
    int idx = blockIdx.x * blockDim.x + threadIdx.x;
    if (idx < 128 * 256) {
        int k = idx / 256, cp = idx % 256;
        Wil[idx] = W[k * 256 + (cp & 1) * 128 + (cp >> 1)];
    }
    if (idx < 256) bil[idx] = b[(idx & 1) * 128 + (idx >> 1)];
}

// alphau[m,i] = sum_k us[m,k] * aW[128+k, i]   (m over TM1*BB rows)
__global__ void alphau_kernel(const float* __restrict__ us,
                              const float* __restrict__ aW) {
    int m = blockIdx.x * blockDim.x + threadIdx.x;
    if (m >= TM1 * BB) return;
    float u[16];
    const float* up = us + (size_t)m * 16;
#pragma unroll
    for (int k = 0; k < 16; k++) u[k] = up[k];
#pragma unroll
    for (int i = 0; i < 16; i++) {
        float s = 0.f;
#pragma unroll
        for (int k = 0; k < 16; k++) s += u[k] * aW[(128 + k) * 16 + i];
        g_alphau[(size_t)m * 16 + i] = s;
    }
}

// ---------------- tf32 tensor GEMM, CTA 128x128, cat3 A operand ----------------
// ACT: 0 none, 1 relu, 2 gauss (W interleaved, N=256, out=mean+exp(lv/2)*eps,
// out stride 128), 3 relu(acc + add[r*N+c]) with add matrix instead of bias.
template <int ACT, bool BIAS>
__global__ __launch_bounds__(256) void tmm(
    const float* __restrict__ s0, int w0,
    const float* __restrict__ s1, int w1,
    const float* __restrict__ s2, int w2,
    const float* __restrict__ W, const float* __restrict__ bias,
    const float* __restrict__ eps, const float* __restrict__ add,
    float* __restrict__ out, int M, int N, int K) {
    __shared__ float As[16][136];
    __shared__ float Bs[16][136];
    const int tid = threadIdx.x;
    const int lane = tid & 31, warp = tid >> 5;
    const int m0 = blockIdx.x * 128, n0 = blockIdx.y * 128;
    const int wm = (warp >> 2) * 64, wn = (warp & 3) * 32;
    const int g = lane >> 2, tg = lane & 3;
    float acc[4][4][4];
#pragma unroll
    for (int i = 0; i < 4; i++)
#pragma unroll
        for (int j = 0; j < 4; j++)
#pragma unroll
            for (int q = 0; q < 4; q++) acc[i][j][q] = 0.f;

    const int nch = K >> 4;
    float4 pa[2], pb[2];

    auto gload = [&](int ch) {
        int kb = ch << 4;
        const float* sp; int sw;
        if (kb < w0)           { sp = s0 + kb;            sw = w0; }
        else if (kb < w0 + w1) { sp = s1 + (kb - w0);      sw = w1; }
        else                   { sp = s2 + (kb - w0 - w1); sw = w2; }
#pragma unroll
        for (int i = 0; i < 2; i++) {
            int idx = tid + (i << 8);
            int r = idx >> 2, c4 = (idx & 3) << 2;
            pa[i] = *(const float4*)(sp + (size_t)(m0 + r) * sw + c4);
            int br = idx >> 5, bc4 = (idx & 31) << 2;
            pb[i] = *(const float4*)(W + (size_t)(kb + br) * N + n0 + bc4);
        }
    };
    auto sstore = [&]() {
#pragma unroll
        for (int i = 0; i < 2; i++) {
            int idx = tid + (i << 8);
            int r = idx >> 2, c4 = (idx & 3) << 2;
            As[c4 + 0][r] = tf32r(pa[i].x); As[c4 + 1][r] = tf32r(pa[i].y);
            As[c4 + 2][r] = tf32r(pa[i].z); As[c4 + 3][r] = tf32r(pa[i].w);
            int br = idx >> 5, bc4 = (idx & 31) << 2;
            float4 t;
            t.x = tf32r(pb[i].x); t.y = tf32r(pb[i].y);
            t.z = tf32r(pb[i].z); t.w = tf32r(pb[i].w);
            *(float4*)&Bs[br][bc4] = t;
        }
    };

    gload(0);
    for (int ch = 0; ch < nch; ch++) {
        __syncthreads();
        sstore();
        __syncthreads();
        if (ch + 1 < nch) gload(ch + 1);
#pragma unroll
        for (int kk = 0; kk < 16; kk += 8) {
            float a[4][4], b[4][2];
#pragma unroll
            for (int mt = 0; mt < 4; mt++) {
                int r = wm + mt * 16 + g;
                a[mt][0] = As[kk + tg][r];
                a[mt][1] = As[kk + tg][r + 8];
                a[mt][2] = As[kk + tg + 4][r];
                a[mt][3] = As[kk + tg + 4][r + 8];
            }
#pragma unroll
            for (int nt = 0; nt < 4; nt++) {
                int c = wn + nt * 8 + g;
                b[nt][0] = Bs[kk + tg][c];
                b[nt][1] = Bs[kk + tg + 4][c];
            }
#pragma unroll
            for (int mt = 0; mt < 4; mt++)
#pragma unroll
                for (int nt = 0; nt < 4; nt++)
                    mma8(acc[mt][nt], a[mt], b[nt]);
        }
    }

#pragma unroll
    for (int mt = 0; mt < 4; mt++) {
#pragma unroll
        for (int nt = 0; nt < 4; nt++) {
            int r = m0 + wm + mt * 16 + g;
            int c = n0 + wn + nt * 8 + 2 * tg;
            if (ACT == 2) {
                int j = c >> 1;
                float bm = bias[c], bl = bias[c + 1];
                float mean0 = acc[mt][nt][0] + bm, lv0 = acc[mt][nt][1] + bl;
                float mean1 = acc[mt][nt][2] + bm, lv1 = acc[mt][nt][3] + bl;
                out[(size_t)r * 128 + j] =
                    mean0 + expf(0.5f * lv0) * eps[(size_t)r * 128 + j];
                out[(size_t)(r + 8) * 128 + j] =
                    mean1 + expf(0.5f * lv1) * eps[(size_t)(r + 8) * 128 + j];
            } else {
                float2 v0 = make_float2(acc[mt][nt][0], acc[mt][nt][1]);
                float2 v1 = make_float2(acc[mt][nt][2], acc[mt][nt][3]);
                if (ACT == 3) {
                    float2 a0 = *(const float2*)(add + (size_t)r * N + c);
                    float2 a1 = *(const float2*)(add + (size_t)(r + 8) * N + c);
                    v0.x += a0.x; v0.y += a0.y; v1.x += a1.x; v1.y += a1.y;
                } else if (BIAS) {
                    float bx = bias[c], by = bias[c + 1];
                    v0.x += bx; v0.y += by; v1.x += bx; v1.y += by;
                }
                if (ACT == 1 || ACT == 3) {
                    v0.x = fmaxf(v0.x, 0.f); v0.y = fmaxf(v0.y, 0.f);
                    v1.x = fmaxf(v1.x, 0.f); v1.y = fmaxf(v1.y, 0.f);
                }
                *(float2*)(out + (size_t)r * N + c) = v0;
                *(float2*)(out + (size_t)(r + 8) * N + c) = v1;
            }
        }
    }
}

// ---------------- fused tf32 LSTM step (h-part only; x-part precomputed) ----
// gates = Gx_t + h @ WhP + b; cell update in epilogue.
__global__ __launch_bounds__(256) void lstm_step(
    const float* __restrict__ gx, const float* __restrict__ hin,
    float* __restrict__ c, float* __restrict__ hout) {
    __shared__ float As[16][136];
    __shared__ float Bs[16][136];
    const int tid = threadIdx.x;
    const int lane = tid & 31, warp = tid >> 5;
    const int m0 = blockIdx.x * 128, n0 = blockIdx.y * 128;
    const int wm = (warp >> 2) * 64, wn = (warp & 3) * 32;
    const int g = lane >> 2, tg = lane & 3;
    float acc[4][4][4];
#pragma unroll
    for (int i = 0; i < 4; i++)
#pragma unroll
        for (int j = 0; j < 4; j++)
#pragma unroll
            for (int q = 0; q < 4; q++) acc[i][j][q] = 0.f;

    float4 pa[2], pb[2];
    auto gload = [&](int ch) {
        int kb = ch << 4;
#pragma unroll
        for (int i = 0; i < 2; i++) {
            int idx = tid + (i << 8);
            int r = idx >> 2, c4 = (idx & 3) << 2;
            pa[i] = *(const float4*)(hin + (size_t)(m0 + r) * 128 + kb + c4);
            int br = idx >> 5, bc4 = (idx & 31) << 2;
            pb[i] = *(const float4*)(g_WhP + (size_t)(kb + br) * 512 + n0 + bc4);
        }
    };
    auto sstore = [&]() {
#pragma unroll
        for (int i = 0; i < 2; i++) {
            int idx = tid + (i << 8);
            int r = idx >> 2, c4 = (idx & 3) << 2;
            As[c4 + 0][r] = tf32r(pa[i].x); As[c4 + 1][r] = tf32r(pa[i].y);
            As[c4 + 2][r] = tf32r(pa[i].z); As[c4 + 3][r] = tf32r(pa[i].w);
            int br = idx >> 5, bc4 = (idx & 31) << 2;
            float4 t;
            t.x = tf32r(pb[i].x); t.y = tf32r(pb[i].y);
            t.z = tf32r(pb[i].z); t.w = tf32r(pb[i].w);
            *(float4*)&Bs[br][bc4] = t;
        }
    };

    gload(0);
    for (int ch = 0; ch < 8; ch++) {
        __syncthreads();
        sstore();
        __syncthreads();
        if (ch + 1 < 8) gload(ch + 1);
#pragma unroll
        for (int kk = 0; kk < 16; kk += 8) {
            float a[4][4], b[4][2];
#pragma unroll
            for (int mt = 0; mt < 4; mt++) {
                int r = wm + mt * 16 + g;
                a[mt][0] = As[kk + tg][r];
                a[mt][1] = As[kk + tg][r + 8];
                a[mt][2] = As[kk + tg + 4][r];
                a[mt][3] = As[kk + tg + 4][r + 8];
            }
#pragma unroll
            for (int nt = 0; nt < 4; nt++) {
                int cc = wn + nt * 8 + g;
                b[nt][0] = Bs[kk + tg][cc];
                b[nt][1] = Bs[kk + tg + 4][cc];
            }
#pragma unroll
            for (int mt = 0; mt < 4; mt++)
#pragma unroll
                for (int nt = 0; nt < 4; nt++)
                    mma8(acc[mt][nt], a[mt], b[nt]);
        }
    }

    const int jbase = ((n0 + wn) >> 5) * 8 + 2 * tg;
    float bs[4][2];
#pragma unroll
    for (int nt = 0; nt < 4; nt++) {
        bs[nt][0] = g_bstack[n0 + wn + nt * 8 + 2 * tg];
        bs[nt][1] = g_bstack[n0 + wn + nt * 8 + 2 * tg + 1];
    }
#pragma unroll
    for (int mt = 0; mt < 4; mt++) {
#pragma unroll
        for (int half = 0; half < 2; half++) {
            int row = m0 + wm + mt * 16 + g + half * 8;
            float2 gxv[4];
#pragma unroll
            for (int nt = 0; nt < 4; nt++)
                gxv[nt] = *(const float2*)(gx + (size_t)row * 512 + n0 + wn + nt * 8 + 2 * tg);
#pragma unroll
            for (int b = 0; b < 2; b++) {
                int q = half * 2 + b;
                float gi = acc[mt][0][q] + bs[0][b] + (b ? gxv[0].y : gxv[0].x);
                float gf = acc[mt][1][q] + bs[1][b] + (b ? gxv[1].y : gxv[1].x);
                float gg = acc[mt][2][q] + bs[2][b] + (b ? gxv[2].y : gxv[2].x);
                float go = acc[mt][3][q] + bs[3][b] + (b ? gxv[3].y : gxv[3].x);
                float si = 1.f / (1.f + expf(-gi));
                float sf = 1.f / (1.f + expf(-gf));
                float so = 1.f / (1.f + expf(-go));
                size_t idx = (size_t)row * 128 + jbase + b;
                float cn = sf * c[idx] + si * tanhf(gg);
                c[idx] = cn;
                hout[idx] = so * tanhf(cn);
            }
        }
    }
}

// ---------------- fused alpha softmax + mix reduce ----------------
// block handles 2 batch rows; alpha logits from z (smem) + precomputed u-part.
__global__ __launch_bounds__(256) void reduce_alpha(
    const float* __restrict__ P, const float* __restrict__ z,
    const float* __restrict__ aW, const float* __restrict__ alphau_t,
    float* __restrict__ znext) {
    __shared__ float aWs[128 * 16];
    __shared__ float zsh[2][128];
    __shared__ float sa[2][16];
    const int tid = threadIdx.x;
    const int sub = tid >> 7, lt = tid & 127;
    const int b = blockIdx.x * 2 + sub;
    for (int i = tid; i < 128 * 16; i += 256) aWs[i] = aW[i];
    zsh[sub][lt] = z[(size_t)b * 128 + lt];
    __syncthreads();
    if (lt < 16) {
        float acc = alphau_t[(size_t)b * 16 + lt];
#pragma unroll 8
        for (int k = 0; k < 128; k++) acc += zsh[sub][k] * aWs[k * 16 + lt];
        sa[sub][lt] = acc;
    }
    __syncthreads();
    if (lt < 16) {
        float mx = -1e30f;
#pragma unroll
        for (int q = 0; q < 16; q++) mx = fmaxf(mx, sa[sub][q]);
        float e = expf(sa[sub][lt] - mx);
        zsh[sub][lt] = e;   // reuse zsh as temp (z no longer needed)
    }
    __syncthreads();
    if (lt < 16) {
        float s = 0.f;
#pragma unroll
        for (int q = 0; q < 16; q++) s += zsh[sub][q];
        sa[sub][lt] = zsh[sub][lt] / s;
    }
    __syncthreads();
    const float* pb = P + (size_t)b * 2048 + lt;
    float s = 0.f;
#pragma unroll
    for (int i = 0; i < 16; i++) s += sa[sub][i] * pb[i * 128];
    znext[(size_t)b * 128 + lt] = s;
}

// ---------------- host orchestration ----------------
extern "C" void kernel_launch(void* const* d_in, const int* in_sizes, int n_in,
                              void* d_out, int out_size) {
    const float* xs      = (const float*)d_in[0];
    const float* us      = (const float*)d_in[1];
    const float* eps1    = (const float*)d_in[2];
    const float* eps     = (const float*)d_in[3];
    const float* lstm_Wx = (const float*)d_in[4];
    const float* lstm_Wh = (const float*)d_in[5];
    const float* lstm_b  = (const float*)d_in[6];
    const float* init_W1 = (const float*)d_in[7];
    const float* init_b1 = (const float*)d_in[8];
    const float* init_W2 = (const float*)d_in[9];
    const float* init_b2 = (const float*)d_in[10];
    const float* trans_W1= (const float*)d_in[11];
    const float* trans_b1= (const float*)d_in[12];
    const float* trans_W2= (const float*)d_in[13];
    const float* trans_b2= (const float*)d_in[14];
    const float* obs_W1  = (const float*)d_in[15];
    const float* obs_b1  = (const float*)d_in[16];
    const float* obs_W2  = (const float*)d_in[17];
    const float* obs_b2  = (const float*)d_in[18];
    const float* rec_W1  = (const float*)d_in[19];
    const float* rec_b1  = (const float*)d_in[20];
    const float* rec_W2  = (const float*)d_in[21];
    const float* rec_b2  = (const float*)d_in[22];
    const float* alpha_W = (const float*)d_in[23];
    const float* Abank   = (const float*)d_in[24];
    const float* Bbank   = (const float*)d_in[25];
    const float* Cbank   = (const float*)d_in[26];

    float *h0, *h1, *c, *hbuf, *rbuf, *wbuf, *w1buf, *P;
    float *Wil_i, *Wil_r, *bil_i, *bil_r, *Mbig, *Gx, *Rxu, *alphau, *Hobs, *WxP;
    cudaGetSymbolAddress((void**)&h0, g_h0);
    cudaGetSymbolAddress((void**)&h1, g_h1);
    cudaGetSymbolAddress((void**)&c, g_c);
    cudaGetSymbolAddress((void**)&hbuf, g_hbuf);
    cudaGetSymbolAddress((void**)&rbuf, g_rbuf);
    cudaGetSymbolAddress((void**)&wbuf, g_wbuf);
    cudaGetSymbolAddress((void**)&w1buf, g_w1);
    cudaGetSymbolAddress((void**)&P, g_P);
    cudaGetSymbolAddress((void**)&Mbig, g_Mbig);
    cudaGetSymbolAddress((void**)&Wil_i, g_W2il_init);
    cudaGetSymbolAddress((void**)&Wil_r, g_W2il_rec);
    cudaGetSymbolAddress((void**)&bil_i, g_b2il_init);
    cudaGetSymbolAddress((void**)&bil_r, g_b2il_rec);
    cudaGetSymbolAddress((void**)&Gx, g_Gx);
    cudaGetSymbolAddress((void**)&Rxu, g_Rxu);
    cudaGetSymbolAddress((void**)&alphau, g_alphau);
    cudaGetSymbolAddress((void**)&Hobs, g_Hobs);
    cudaGetSymbolAddress((void**)&WxP, g_WxP);   // FIX: device address, not host shadow

    cudaMemsetAsync(h0, 0, sizeof(float) * BB * HH);
    cudaMemsetAsync(c, 0, sizeof(float) * BB * HH);

    build_wstack<<<(128 * 512 + 255) / 256, 256>>>(lstm_Wx, lstm_Wh, lstm_b);
    build_mbig<<<(272 * 2048 + 255) / 256, 256>>>(Abank, Bbank, Cbank);
    build_w2il<<<(128 * 256 + 255) / 256, 256>>>(init_W2, init_b2, Wil_i, bil_i);
    build_w2il<<<(128 * 256 + 255) / 256, 256>>>(rec_W2, rec_b2, Wil_r, bil_r);
    alphau_kernel<<<(TM1 * BB + 255) / 256, 256>>>(us, alpha_W);

    // batched x-part of LSTM gates for all t
    tmm<0, false><<<dim3(TT * BB / 128, 4), 256>>>(
        xs, 128, nullptr, 0, nullptr, 0, WxP, nullptr, nullptr, nullptr,
        Gx, TT * BB, 512, 128);
    // batched [x_{t+1}|u_t] part of recognition stage 1 (+bias)
    tmm<0, true><<<dim3(TM1 * BB / 128, 1), 256>>>(
        xs + (size_t)BB * OBSD, 128, us, 16, nullptr, 0,
        rec_W1 + 128 * 128, rec_b1, nullptr, nullptr, Rxu, TM1 * BB, 128, 144);

    // LSTM over T (ping-pong h)
    dim3 gLSTM(BB / 128, 4);
    for (int t = 0; t < TT; t++) {
        const float* hin = (t & 1) ? h1 : h0;
        float* hout      = (t & 1) ? h0 : h1;
        lstm_step<<<gLSTM, 256>>>(Gx + (size_t)t * BB * 512, hin, c, hout);
    }
    float* hfin = h0;  // t=63 (odd) wrote h0

    float* zs   = (float*)d_out;
    float* xrec = zs + (size_t)TT * BB * LAT;

    dim3 g1(BB / 128, 1), g2(BB / 128, 2), gMix(BB / 128, 16);
    // init network
    tmm<1, true><<<g1, 256>>>(hfin, 128, nullptr, 0, nullptr, 0,
                              init_W1, init_b1, nullptr, nullptr, hbuf, BB, 128, 128);
    tmm<2, true><<<g2, 256>>>(hbuf, 128, nullptr, 0, nullptr, 0,
                              Wil_i, bil_i, eps1, nullptr, w1buf, BB, 256, 128);
    tmm<1, true><<<g1, 256>>>(w1buf, 128, nullptr, 0, nullptr, 0,
                              trans_W1, trans_b1, nullptr, nullptr, hbuf, BB, 128, 128);
    tmm<0, true><<<g1, 256>>>(hbuf, 128, nullptr, 0, nullptr, 0,
                              trans_W2, trans_b2, nullptr, nullptr, zs, BB, 128, 128);

    // scan: 4 kernels per step
    for (int t = 0; t < TM1; t++) {
        const float* z = zs + (size_t)t * BB * LAT;
        float* zn      = zs + (size_t)(t + 1) * BB * LAT;
        // rec stage1: relu(z @ recW1[0:128] + Rxu_t)
        tmm<3, false><<<g1, 256>>>(z, 128, nullptr, 0, nullptr, 0,
                                   rec_W1, nullptr, nullptr,
                                   Rxu + (size_t)t * BB * HH, rbuf, BB, 128, 128);
        // gauss sample
        tmm<2, true><<<g2, 256>>>(rbuf, 128, nullptr, 0, nullptr, 0,
                                  Wil_r, bil_r, eps + (size_t)t * BB * LAT,
                                  nullptr, wbuf, BB, 256, 128);
        // P = [z,u,w] @ Mbig
        tmm<0, false><<<gMix, 256>>>(z, 128, us + (size_t)t * BB * CTRL, 16,
                                     wbuf, 128, Mbig, nullptr, nullptr, nullptr,
                                     P, BB, 2048, 272);
        // fused alpha softmax + weighted reduce
        reduce_alpha<<<BB / 2, 256>>>(P, z, alpha_W,
                                      alphau + (size_t)t * BB * NMATD, zn);
    }

    // batched observation network over all z_0..z_62
    tmm<1, true><<<dim3(TM1 * BB / 128, 1), 256>>>(
        zs, 128, nullptr, 0, nullptr, 0, obs_W1, obs_b1, nullptr, nullptr,
        Hobs, TM1 * BB, 128, 128);
    tmm<0, true><<<dim3(TM1 * BB / 128, 1), 256>>>(
        Hobs, 128, nullptr, 0, nullptr, 0, obs_W2, obs_b2, nullptr, nullptr,
        xrec, TM1 * BB, 128, 128);
}